// round 15
// baseline (speedup 1.0000x reference)
#include <cuda_runtime.h>
#include <cuda_bf16.h>
#include <cstdint>

// Problem constants
#define BATCH       256
#define DIM         256
#define NUM_TRUE    1024
#define NUM_SAMPLED 16384
#define LOG_RANGE   11.5129354649202280f

// GEMM tiling: block tile 64(m) x 64(n), FULL K=256 staged in smem
#define BM   64
#define BN   64
#define SLDA 264                     // smem row stride in bf16 elems (528 B)
#define A_SM_BYTES (BM * SLDA * 2)   // 33792
#define SMEM_DYN (2 * A_SM_BYTES + 64 * 4 + 128 * 4)   // A + B + soff + red2

// ---------------- device scratch ----------------
__device__ __nv_bfloat16 g_Wg[NUM_SAMPLED * DIM];
__device__ __nv_bfloat16 g_Abf[BATCH * DIM];
__device__ float g_off_sampled[NUM_SAMPLED];
__device__ float g_true_part[3 * BATCH];     // quarters 0-2: [qt*256 + b]

// ---------------- math helpers (mirror reference numerics) ----------------
__device__ __forceinline__ float neg_log_ec(float idf) {
    float p  = logf((idf + 2.0f) / (idf + 1.0f)) / LOG_RANGE;
    float ec = -expm1f(16384.0f * log1pf(-p));
    return -logf(ec);
}
__device__ __forceinline__ float softplus0(float l) {
    return fmaxf(l, 0.0f) + log1pf(expf(-fabsf(l)));
}
__device__ __forceinline__ float sigmoid_xent(float l, float t) {
    return fmaxf(l, 0.0f) - l * t + log1pf(expf(-fabsf(l)));
}

// ---------------- PTX helpers ----------------
__device__ __forceinline__ void ldsm_x4(uint32_t& r0, uint32_t& r1, uint32_t& r2, uint32_t& r3,
                                        uint32_t addr) {
    asm volatile("ldmatrix.sync.aligned.m8n8.x4.shared.b16 {%0,%1,%2,%3}, [%4];\n"
                 : "=r"(r0), "=r"(r1), "=r"(r2), "=r"(r3) : "r"(addr));
}
__device__ __forceinline__ void mma16816(float* c,
                                         uint32_t a0, uint32_t a1, uint32_t a2, uint32_t a3,
                                         uint32_t b0, uint32_t b1) {
    asm volatile("mma.sync.aligned.m16n8k16.row.col.f32.bf16.bf16.f32 "
                 "{%0,%1,%2,%3}, {%4,%5,%6,%7}, {%8,%9}, {%0,%1,%2,%3};\n"
                 : "+f"(c[0]), "+f"(c[1]), "+f"(c[2]), "+f"(c[3])
                 : "r"(a0), "r"(a1), "r"(a2), "r"(a3), "r"(b0), "r"(b1));
}

// ---------------- true-logits worker (one quarter of one batch row) ------
__device__ __forceinline__ float true_quarter(const float* __restrict__ A,
                                              const float* __restrict__ W,
                                              const float* __restrict__ bias,
                                              const int*   __restrict__ labels,
                                              int b, int qt, int wid, int lane) {
    const float4* arow = (const float4*)(A + b * DIM);
    const float4 x0 = __ldg(arow + lane);
    const float4 x1 = __ldg(arow + lane + 32);

    const int* lab_base = labels + b * NUM_TRUE + qt * 256 + wid * 32;
    const float tt = 1.0f / (float)NUM_TRUE;

    const int labv  = __ldg(lab_base + lane);
    const float offv = __ldg(bias + labv) + neg_log_ec((float)labv);
    float mylogit = 0.0f;
#pragma unroll 4
    for (int jp = 0; jp < 16; jp++) {
        int lab0 = __shfl_sync(0xffffffff, labv, jp);
        int lab1 = __shfl_sync(0xffffffff, labv, jp + 16);
        const float4* wr0 = (const float4*)(W + (size_t)lab0 * DIM);
        const float4* wr1 = (const float4*)(W + (size_t)lab1 * DIM);
        float4 u0a = __ldg(wr0 + lane);
        float4 u0b = __ldg(wr0 + lane + 32);
        float4 u1a = __ldg(wr1 + lane);
        float4 u1b = __ldg(wr1 + lane + 32);
        float d0 = u0a.x * x0.x;
        d0 = fmaf(u0a.y, x0.y, d0); d0 = fmaf(u0a.z, x0.z, d0);
        d0 = fmaf(u0a.w, x0.w, d0);
        d0 = fmaf(u0b.x, x1.x, d0); d0 = fmaf(u0b.y, x1.y, d0);
        d0 = fmaf(u0b.z, x1.z, d0); d0 = fmaf(u0b.w, x1.w, d0);
        float d1 = u1a.x * x0.x;
        d1 = fmaf(u1a.y, x0.y, d1); d1 = fmaf(u1a.z, x0.z, d1);
        d1 = fmaf(u1a.w, x0.w, d1);
        d1 = fmaf(u1b.x, x1.x, d1); d1 = fmaf(u1b.y, x1.y, d1);
        d1 = fmaf(u1b.z, x1.z, d1); d1 = fmaf(u1b.w, x1.w, d1);
        d0 += __shfl_xor_sync(0xffffffff, d0, 16);
        d1 += __shfl_xor_sync(0xffffffff, d1, 16);
        float m = (lane < 16) ? d0 : d1;
        m += __shfl_xor_sync(0xffffffff, m, 8);
        m += __shfl_xor_sync(0xffffffff, m, 4);
        m += __shfl_xor_sync(0xffffffff, m, 2);
        m += __shfl_xor_sync(0xffffffff, m, 1);
        if ((lane & 15) == jp) mylogit = m;
    }
    float acc = sigmoid_xent(mylogit + offv, tt);
    acc += __shfl_xor_sync(0xffffffff, acc, 16);
    acc += __shfl_xor_sync(0xffffffff, acc, 8);
    acc += __shfl_xor_sync(0xffffffff, acc, 4);
    acc += __shfl_xor_sync(0xffffffff, acc, 2);
    acc += __shfl_xor_sync(0xffffffff, acc, 1);
    return acc;   // valid in lane 0 of each warp
}

// ---------------- kernel 1: convert (even blocks) + true qt 0-2 (odd) ----
#define WG_UNITS (NUM_SAMPLED * (DIM / 4))
#define A_UNITS  (BATCH * (DIM / 4))
#define TOTAL_UNITS (WG_UNITS + A_UNITS + BATCH)

__global__ __launch_bounds__(256, 4)
void prep_true_kernel(const float* __restrict__ A,
                      const float* __restrict__ W,
                      const float* __restrict__ bias,
                      const int*   __restrict__ labels,
                      const int*   __restrict__ sampled,
                      float*       __restrict__ out) {
    const int blk  = blockIdx.x;
    const int tid  = threadIdx.x;
    const int lane = tid & 31;
    const int wid  = tid >> 5;
    const int id   = blk >> 1;      // 0..767 per role

    if ((blk & 1) == 0) {
        // convert role: grid-stride over units (768 blocks)
        for (int u = id * 256 + tid; u < TOTAL_UNITS; u += 768 * 256) {
            if (u < WG_UNITS) {
                int row = u >> 6, q = u & 63;
                int sid = __ldg(&sampled[row]);
                float4 v = __ldg((const float4*)(W + (size_t)sid * DIM) + q);
                __nv_bfloat162* dst = (__nv_bfloat162*)(g_Wg + row * DIM + q * 4);
                dst[0] = __floats2bfloat162_rn(v.x, v.y);
                dst[1] = __floats2bfloat162_rn(v.z, v.w);
                if (q == 0) g_off_sampled[row] = bias[sid] + neg_log_ec((float)sid);
            } else if (u < WG_UNITS + A_UNITS) {
                int u2 = u - WG_UNITS;
                int row = u2 >> 6, q = u2 & 63;
                float4 v = __ldg((const float4*)(A + row * DIM) + q);
                __nv_bfloat162* dst = (__nv_bfloat162*)(g_Abf + row * DIM + q * 4);
                dst[0] = __floats2bfloat162_rn(v.x, v.y);
                dst[1] = __floats2bfloat162_rn(v.z, v.w);
            } else {
                out[u - WG_UNITS - A_UNITS] = 0.0f;
            }
        }
    } else {
        // true role: quarters 0..2; id in 0..767
        const int b  = id & 255;
        const int qt = id >> 8;     // 0,1,2
        float acc = true_quarter(A, W, bias, labels, b, qt, wid, lane);
        __shared__ float tred[8];
        if (lane == 0) tred[wid] = acc;
        __syncthreads();
        if (tid == 0) {
            float s = 0.0f;
#pragma unroll
            for (int i = 0; i < 8; i++) s += tred[i];
            g_true_part[qt * 256 + b] = s;
        }
    }
}

// ---------------- kernel 2: sync-free full-K GEMM (4:1 with true qt 3) ----
__global__ __launch_bounds__(256, 3)
void gemm_true_kernel(const float* __restrict__ A,
                      const float* __restrict__ W,
                      const float* __restrict__ bias,
                      const int*   __restrict__ labels,
                      float* __restrict__ out) {
    extern __shared__ char smem[];
    const int blk  = blockIdx.x;
    const int tid  = threadIdx.x;
    const int lane = tid & 31;
    const int wid  = tid >> 5;

    if (blk % 5 == 0) {
        // ===== true role: quarter 3, 256 blocks =====
        const int b = blk / 5;
        float acc = true_quarter(A, W, bias, labels, b, 3, wid, lane);
        float* tred = (float*)smem;
        if (lane == 0) tred[wid] = acc;
        __syncthreads();
        if (tid == 0) {
            float s = 0.0f;
#pragma unroll
            for (int i = 0; i < 8; i++) s += tred[i];
            atomicAdd(out + b, s);
        }
        return;
    }

    // ===== GEMM role: gid 0..1023 =====
    const int gid = (blk / 5) * 4 + (blk % 5) - 1;
    const int bn = gid >> 2;             // 0..255
    const int bm = gid & 3;              // 0..3
    const int m0 = bm * BM, n0 = bn * BN;

    char* smA = smem;
    char* smB = smem + A_SM_BYTES;
    float* soff = (float*)(smem + 2 * A_SM_BYTES);
    float* red2 = soff + 64;             // [2][64]

    if (tid < BN) soff[tid] = g_off_sampled[n0 + tid];

    // fill: full 64x256 bf16 tiles, stride 264 elems (528 B)
    {
        const uint4* srcA = (const uint4*)(g_Abf + m0 * DIM);
        const uint4* srcB = (const uint4*)(g_Wg + n0 * DIM);
#pragma unroll
        for (int i = tid; i < 2048; i += 256) {
            int row = i >> 5, c = i & 31;
            *(uint4*)(smA + row * 528 + c * 16) = srcA[row * 32 + c];
            *(uint4*)(smB + row * 528 + c * 16) = srcB[row * 32 + c];
        }
    }
    __syncthreads();

    const uint32_t sA = (uint32_t)__cvta_generic_to_shared(smA);
    const uint32_t sB = (uint32_t)__cvta_generic_to_shared(smB);

    // warp grid 4(m) x 2(n); warp tile 16x32
    const int mw = (wid >> 1) * 16;
    const int nw = (wid & 1) * 32;
    const int nwarp = wid & 1;

    float c[4][4];
#pragma unroll
    for (int j = 0; j < 4; j++)
#pragma unroll
        for (int e = 0; e < 4; e++) c[j][e] = 0.0f;

    // sync-free mainloop: 16 k16-steps fully unrolled
#pragma unroll
    for (int kt = 0; kt < 8; kt++) {
#pragma unroll
        for (int ks = 0; ks < 2; ks++) {
            const int colb = (kt * 32 + ks * 16) * 2;
            uint32_t a[4], b[2][4];
            {
                uint32_t addr = sA + (mw + (lane & 15)) * 528 + colb + (lane >> 4) * 16;
                ldsm_x4(a[0], a[1], a[2], a[3], addr);
            }
#pragma unroll
            for (int p = 0; p < 2; p++) {
                uint32_t addr = sB +
                    (nw + p * 16 + (lane & 7) + ((lane >> 4) & 1) * 8) * 528 +
                    colb + ((lane >> 3) & 1) * 16;
                ldsm_x4(b[p][0], b[p][1], b[p][2], b[p][3], addr);
            }
#pragma unroll
            for (int nt = 0; nt < 4; nt++) {
                int p = nt >> 1, h = nt & 1;
                mma16816(c[nt], a[0], a[1], a[2], a[3],
                         b[p][h * 2], b[p][h * 2 + 1]);
            }
        }
    }

    // epilogue: +offset, softplus, per-row sums
    float rs[2] = {0.f, 0.f};
#pragma unroll
    for (int nt = 0; nt < 4; nt++) {
        int colbase = nw + nt * 8 + (lane & 3) * 2;
#pragma unroll
        for (int e = 0; e < 4; e++) {
            float l = c[nt][e] + soff[colbase + (e & 1)];
            rs[e >> 1] += softplus0(l);
        }
    }
#pragma unroll
    for (int i = 0; i < 2; i++) {
        rs[i] += __shfl_xor_sync(0xffffffff, rs[i], 1);
        rs[i] += __shfl_xor_sync(0xffffffff, rs[i], 2);
    }
    if ((lane & 3) == 0) {
        int r = lane >> 2;
        red2[nwarp * 64 + mw + r]     = rs[0];
        red2[nwarp * 64 + mw + r + 8] = rs[1];
    }
    __syncthreads();
    if (tid < BM) {
        const int row = m0 + tid;
        float v = red2[tid] + red2[64 + tid];
        if (bn == 0)
            v += g_true_part[row] + g_true_part[256 + row] + g_true_part[512 + row];
        atomicAdd(out + row, v);
    }
}

// ---------------- launch ---------------------------------------------------
extern "C" void kernel_launch(void* const* d_in, const int* in_sizes, int n_in,
                              void* d_out, int out_size) {
    const float* inputs  = (const float*)d_in[0];
    const float* w       = (const float*)d_in[1];
    const float* bias    = (const float*)d_in[2];
    const int*   labels  = (const int*)d_in[3];
    const int*   sampled = (const int*)d_in[4];
    float*       out     = (float*)d_out;

    cudaFuncSetAttribute(gemm_true_kernel,
                         cudaFuncAttributeMaxDynamicSharedMemorySize, SMEM_DYN);
    prep_true_kernel<<<1536, 256>>>(inputs, w, bias, labels, sampled, out);
    gemm_true_kernel<<<1280, 256, SMEM_DYN>>>(inputs, w, bias, labels, out);
}

// round 16
// speedup vs baseline: 1.1236x; 1.1236x over previous
#include <cuda_runtime.h>
#include <cuda_bf16.h>
#include <cstdint>

// Problem constants
#define BATCH       256
#define DIM         256
#define NUM_TRUE    1024
#define NUM_SAMPLED 16384
#define LOG_RANGE   11.5129354649202280f

// GEMM tiling (bf16 tensor core): block tile 64(m) x 64(n), k-tiles of 32
#define BM   64
#define BN   64
#define NKT  8
#define PAD  40                     // padded smem row (bf16): 80B stride

// ---------------- device scratch ----------------
__device__ __nv_bfloat16 g_Abf[BATCH * DIM];
__device__ float g_off_sampled[NUM_SAMPLED];

// ---------------- math helpers (mirror reference numerics) ----------------
__device__ __forceinline__ float neg_log_ec(float idf) {
    float p  = logf((idf + 2.0f) / (idf + 1.0f)) / LOG_RANGE;
    float ec = -expm1f(16384.0f * log1pf(-p));
    return -logf(ec);
}
__device__ __forceinline__ float softplus0(float l) {
    return fmaxf(l, 0.0f) + log1pf(expf(-fabsf(l)));
}
__device__ __forceinline__ float sigmoid_xent(float l, float t) {
    return fmaxf(l, 0.0f) - l * t + log1pf(expf(-fabsf(l)));
}

// ---------------- PTX helpers ----------------
__device__ __forceinline__ void ldsm_x4(uint32_t& r0, uint32_t& r1, uint32_t& r2, uint32_t& r3,
                                        uint32_t addr) {
    asm volatile("ldmatrix.sync.aligned.m8n8.x4.shared.b16 {%0,%1,%2,%3}, [%4];\n"
                 : "=r"(r0), "=r"(r1), "=r"(r2), "=r"(r3) : "r"(addr));
}
__device__ __forceinline__ void mma16816(float* c,
                                         uint32_t a0, uint32_t a1, uint32_t a2, uint32_t a3,
                                         uint32_t b0, uint32_t b1) {
    asm volatile("mma.sync.aligned.m16n8k16.row.col.f32.bf16.bf16.f32 "
                 "{%0,%1,%2,%3}, {%4,%5,%6,%7}, {%8,%9}, {%0,%1,%2,%3};\n"
                 : "+f"(c[0]), "+f"(c[1]), "+f"(c[2]), "+f"(c[3])
                 : "r"(a0), "r"(a1), "r"(a2), "r"(a3), "r"(b0), "r"(b1));
}
// pack 8 f32 -> 8 bf16 (one uint4)
__device__ __forceinline__ uint4 cvt8(float4 a, float4 b) {
    uint4 r;
    __nv_bfloat162 h0 = __floats2bfloat162_rn(a.x, a.y);
    __nv_bfloat162 h1 = __floats2bfloat162_rn(a.z, a.w);
    __nv_bfloat162 h2 = __floats2bfloat162_rn(b.x, b.y);
    __nv_bfloat162 h3 = __floats2bfloat162_rn(b.z, b.w);
    r.x = *(uint32_t*)&h0; r.y = *(uint32_t*)&h1;
    r.z = *(uint32_t*)&h2; r.w = *(uint32_t*)&h3;
    return r;
}

// ---------------- true-logits worker (one quarter of one batch row) ------
__device__ __forceinline__ float true_quarter(const float* __restrict__ A,
                                              const float* __restrict__ W,
                                              const float* __restrict__ bias,
                                              const int*   __restrict__ labels,
                                              int b, int qt, int wid, int lane) {
    const float4* arow = (const float4*)(A + b * DIM);
    const float4 x0 = __ldg(arow + lane);
    const float4 x1 = __ldg(arow + lane + 32);

    const int* lab_base = labels + b * NUM_TRUE + qt * 256 + wid * 32;
    const float tt = 1.0f / (float)NUM_TRUE;

    const int labv  = __ldg(lab_base + lane);
    const float offv = __ldg(bias + labv) + neg_log_ec((float)labv);
    float mylogit = 0.0f;
#pragma unroll 4
    for (int jp = 0; jp < 16; jp++) {
        int lab0 = __shfl_sync(0xffffffff, labv, jp);
        int lab1 = __shfl_sync(0xffffffff, labv, jp + 16);
        const float4* wr0 = (const float4*)(W + (size_t)lab0 * DIM);
        const float4* wr1 = (const float4*)(W + (size_t)lab1 * DIM);
        float4 u0a = __ldg(wr0 + lane);
        float4 u0b = __ldg(wr0 + lane + 32);
        float4 u1a = __ldg(wr1 + lane);
        float4 u1b = __ldg(wr1 + lane + 32);
        float d0 = u0a.x * x0.x;
        d0 = fmaf(u0a.y, x0.y, d0); d0 = fmaf(u0a.z, x0.z, d0);
        d0 = fmaf(u0a.w, x0.w, d0);
        d0 = fmaf(u0b.x, x1.x, d0); d0 = fmaf(u0b.y, x1.y, d0);
        d0 = fmaf(u0b.z, x1.z, d0); d0 = fmaf(u0b.w, x1.w, d0);
        float d1 = u1a.x * x0.x;
        d1 = fmaf(u1a.y, x0.y, d1); d1 = fmaf(u1a.z, x0.z, d1);
        d1 = fmaf(u1a.w, x0.w, d1);
        d1 = fmaf(u1b.x, x1.x, d1); d1 = fmaf(u1b.y, x1.y, d1);
        d1 = fmaf(u1b.z, x1.z, d1); d1 = fmaf(u1b.w, x1.w, d1);
        d0 += __shfl_xor_sync(0xffffffff, d0, 16);
        d1 += __shfl_xor_sync(0xffffffff, d1, 16);
        float m = (lane < 16) ? d0 : d1;
        m += __shfl_xor_sync(0xffffffff, m, 8);
        m += __shfl_xor_sync(0xffffffff, m, 4);
        m += __shfl_xor_sync(0xffffffff, m, 2);
        m += __shfl_xor_sync(0xffffffff, m, 1);
        if ((lane & 15) == jp) mylogit = m;
    }
    float acc = sigmoid_xent(mylogit + offv, tt);
    acc += __shfl_xor_sync(0xffffffff, acc, 16);
    acc += __shfl_xor_sync(0xffffffff, acc, 8);
    acc += __shfl_xor_sync(0xffffffff, acc, 4);
    acc += __shfl_xor_sync(0xffffffff, acc, 2);
    acc += __shfl_xor_sync(0xffffffff, acc, 1);
    return acc;   // valid in lane 0 of each warp
}

// ---------------- kernel 0: tiny prep: zero out, convert A, offsets -------
__global__ __launch_bounds__(256)
void prep0_kernel(const float* __restrict__ inputs,
                  const float* __restrict__ bias,
                  const int*   __restrict__ sampled,
                  float*       __restrict__ out) {
    const int t = blockIdx.x * 256 + threadIdx.x;   // 0..16383
    // per-sampled offset
    {
        int sid = __ldg(&sampled[t]);
        g_off_sampled[t] = bias[sid] + neg_log_ec((float)sid);
    }
    // A convert: 16384 float4 units
    {
        int row = t >> 6, q = t & 63;
        float4 v = __ldg((const float4*)(inputs + row * DIM) + q);
        __nv_bfloat162* dst = (__nv_bfloat162*)(g_Abf + row * DIM + q * 4);
        dst[0] = __floats2bfloat162_rn(v.x, v.y);
        dst[1] = __floats2bfloat162_rn(v.z, v.w);
    }
    if (t < BATCH) out[t] = 0.0f;
}

// ---------------- mega kernel: GEMM (even, inline B gather) + true (odd) --
struct GemmSmem {
    __nv_bfloat16 As[2][BM][PAD];
    __nv_bfloat16 Bs[2][BN][PAD];
    float soff[BN];
    float red2[2][BM];
    int   ssid[BN];
};
union SmemU {
    GemmSmem g;
    float tred[8];
};

__global__ __launch_bounds__(256, 4)
void mega_kernel(const float* __restrict__ A,
                 const float* __restrict__ W,
                 const float* __restrict__ bias,
                 const int*   __restrict__ labels,
                 const int*   __restrict__ sampled,
                 float*       __restrict__ out) {
    __shared__ SmemU sm;
    const int blk  = blockIdx.x;
    const int tid  = threadIdx.x;
    const int lane = tid & 31;
    const int wid  = tid >> 5;
    const int id   = blk >> 1;      // 0..1023 per role

    if ((blk & 1) == 0) {
        // ================= GEMM path: tile BM=64 x BN=64, inline B gather ==
        const int bn = id >> 2;             // 0..255
        const int bm = id & 3;              // 0..3
        const int m0 = bm * BM, n0 = bn * BN;

        if (tid < BN) {
            sm.g.soff[tid] = g_off_sampled[n0 + tid];
            sm.g.ssid[tid] = __ldg(&sampled[n0 + tid]);
        }
        __syncthreads();

        const int mw = (wid >> 1) * 16;
        const int nw = (wid & 1) * 32;
        const int nwarp = wid & 1;

        // loaders: A tile 64x32 bf16 = 256 x 16B (1/thr); B gathered f32
        const int lr = tid >> 2;    // 0..63
        const int lc = tid & 3;
        const uint4*  gA = (const uint4*)(g_Abf + (m0 + lr) * DIM) + lc;
        const float4* gB = (const float4*)(W + (size_t)sm.g.ssid[lr] * DIM) + lc * 2;

        float c[4][4];
#pragma unroll
        for (int j = 0; j < 4; j++)
#pragma unroll
            for (int e = 0; e < 4; e++) c[j][e] = 0.0f;

        uint4 ra = gA[0];
        uint4 rb = cvt8(__ldg(gB), __ldg(gB + 1));
        *(uint4*)&sm.g.As[0][lr][lc * 8] = ra;
        *(uint4*)&sm.g.Bs[0][lr][lc * 8] = rb;
        __syncthreads();

        const uint32_t sAs = (uint32_t)__cvta_generic_to_shared(&sm.g.As[0][0][0]);
        const uint32_t sBs = (uint32_t)__cvta_generic_to_shared(&sm.g.Bs[0][0][0]);
        const uint32_t tbuf = BM * PAD * 2;

        int buf = 0;
        for (int kt = 0; kt < NKT; kt++) {
            if (kt < NKT - 1) {
                ra = gA[(kt + 1) * 4];
                rb = cvt8(__ldg(gB + (kt + 1) * 8), __ldg(gB + (kt + 1) * 8 + 1));
            }
            const uint32_t baseA = sAs + buf * tbuf;
            const uint32_t baseB = sBs + buf * tbuf;
#pragma unroll
            for (int ks = 0; ks < 2; ks++) {
                uint32_t a[4], b[2][4];
                {
                    uint32_t addr = baseA +
                        ((mw + (lane & 15)) * PAD + ks * 16 + (lane >> 4) * 8) * 2;
                    ldsm_x4(a[0], a[1], a[2], a[3], addr);
                }
#pragma unroll
                for (int p = 0; p < 2; p++) {
                    uint32_t addr = baseB +
                        ((nw + p * 16 + (lane & 7) + ((lane >> 4) & 1) * 8) * PAD +
                         ks * 16 + ((lane >> 3) & 1) * 8) * 2;
                    ldsm_x4(b[p][0], b[p][1], b[p][2], b[p][3], addr);
                }
#pragma unroll
                for (int nt = 0; nt < 4; nt++) {
                    int p = nt >> 1, h = nt & 1;
                    mma16816(c[nt], a[0], a[1], a[2], a[3],
                             b[p][h * 2], b[p][h * 2 + 1]);
                }
            }
            if (kt < NKT - 1) {
                int nb = buf ^ 1;
                *(uint4*)&sm.g.As[nb][lr][lc * 8] = ra;
                *(uint4*)&sm.g.Bs[nb][lr][lc * 8] = rb;
                __syncthreads();
                buf = nb;
            }
        }

        // epilogue: +offset, softplus, per-row sums
        float rs[2] = {0.f, 0.f};
#pragma unroll
        for (int nt = 0; nt < 4; nt++) {
            int colbase = nw + nt * 8 + (lane & 3) * 2;
#pragma unroll
            for (int e = 0; e < 4; e++) {
                float l = c[nt][e] + sm.g.soff[colbase + (e & 1)];
                rs[e >> 1] += softplus0(l);
            }
        }
#pragma unroll
        for (int i = 0; i < 2; i++) {
            rs[i] += __shfl_xor_sync(0xffffffff, rs[i], 1);
            rs[i] += __shfl_xor_sync(0xffffffff, rs[i], 2);
        }
        if ((lane & 3) == 0) {
            int r = lane >> 2;
            sm.g.red2[nwarp][mw + r]     = rs[0];
            sm.g.red2[nwarp][mw + r + 8] = rs[1];
        }
        __syncthreads();
        if (tid < BM)
            atomicAdd(out + m0 + tid, sm.g.red2[0][tid] + sm.g.red2[1][tid]);
    } else {
        // ===== true-logits path: 1024 blocks, each = 1/4 of a batch row =====
        const int b  = id >> 2;
        const int qt = id & 3;

        float acc = true_quarter(A, W, bias, labels, b, qt, wid, lane);
        if (lane == 0) sm.tred[wid] = acc;
        __syncthreads();
        if (tid == 0) {
            float s = 0.0f;
#pragma unroll
            for (int i = 0; i < 8; i++) s += sm.tred[i];
            atomicAdd(out + b, s);
        }
    }
}

// ---------------- launch ---------------------------------------------------
extern "C" void kernel_launch(void* const* d_in, const int* in_sizes, int n_in,
                              void* d_out, int out_size) {
    const float* inputs  = (const float*)d_in[0];
    const float* w       = (const float*)d_in[1];
    const float* bias    = (const float*)d_in[2];
    const int*   labels  = (const int*)d_in[3];
    const int*   sampled = (const int*)d_in[4];
    float*       out     = (float*)d_out;

    prep0_kernel<<<NUM_SAMPLED / 256, 256>>>(inputs, bias, sampled, out);
    mega_kernel<<<2048, 256>>>(inputs, w, bias, labels, sampled, out);
}